// round 4
// baseline (speedup 1.0000x reference)
#include <cuda_runtime.h>
#include <math.h>

#define BB   128
#define NN   512
#define FIN  5
#define HH   64
#define KNN  16
#define COUT 10
#define NODES (BB*NN)

typedef unsigned long long ull;

// ---------------- scratch (device globals: no allocation allowed) ----------------
__device__ float g_h0[NODES*HH];
__device__ float g_h1[NODES*HH];
__device__ float g_A [NODES*HH];
__device__ float g_U [NODES*HH];
__device__ float g_sq[NODES];
__device__ float g_dist[(size_t)BB*NN*NN];   // 134 MB distance scratch
__device__ int   g_knn[NODES*KNN];

__device__ __forceinline__ float elu1(float x) { return x > 0.f ? x : expm1f(x); }

// ---- packed f32x2 helpers (Blackwell FFMA2 via PTX) ----
__device__ __forceinline__ ull pack2(float x, float y) {
    ull r; asm("mov.b64 %0, {%1,%2};" : "=l"(r) : "f"(x), "f"(y)); return r;
}
__device__ __forceinline__ float2 unpack2(ull v) {
    float2 f; asm("mov.b64 {%0,%1}, %2;" : "=f"(f.x), "=f"(f.y) : "l"(v)); return f;
}
__device__ __forceinline__ ull ffma2(ull a, ull b, ull c) {
    ull d; asm("fma.rn.f32x2 %0, %1, %2, %3;" : "=l"(d) : "l"(a), "l"(b), "l"(c)); return d;
}

// ---------------- generic per-node GEMV + ELU ----------------
template<int IN>
__global__ __launch_bounds__(256) void k_lin(const float* __restrict__ in,
                                             const float* __restrict__ W,
                                             const float* __restrict__ b,
                                             float* __restrict__ out)
{
    __shared__ float sW[IN*HH];
    __shared__ float sb[HH];
    int tid = threadIdx.x;
    for (int i = tid; i < IN*HH; i += 256) sW[i] = W[i];
    if (tid < HH) sb[tid] = b[tid];
    __syncthreads();

    int node = blockIdx.x * 256 + tid;
    float v[IN];
#pragma unroll
    for (int d = 0; d < IN; d++) v[d] = in[node*IN + d];

    for (int o = 0; o < HH; o++) {
        float a = sb[o];
#pragma unroll
        for (int d = 0; d < IN; d++) a += v[d] * sW[d*HH + o];
        out[node*HH + o] = elu1(a);
    }
}

// ---------------- EdgeConv layer-0 factorization (unchanged, known good) ----------------
__global__ __launch_bounds__(256) void k_pre(const float* __restrict__ h,
                                             const float* __restrict__ W0,
                                             const float* __restrict__ b0,
                                             float* __restrict__ A,
                                             float* __restrict__ U)
{
    __shared__ float sWb[HH*HH];
    __shared__ float sWd[HH*HH];
    __shared__ float sb[HH];
    int tid = threadIdx.x;
    for (int i = tid; i < HH*HH; i += 256) {
        float wa = W0[i];
        float wb = W0[HH*HH + i];
        sWb[i] = wb;
        sWd[i] = wa - wb;
    }
    if (tid < HH) sb[tid] = b0[tid];
    __syncthreads();

    int node = blockIdx.x * 256 + tid;
    float hv[HH];
#pragma unroll
    for (int d = 0; d < HH; d++) hv[d] = h[node*HH + d];

    for (int o = 0; o < HH; o++) {
        float au = 0.f, ad = sb[o];
#pragma unroll
        for (int d = 0; d < HH; d++) {
            au += hv[d] * sWb[d*HH + o];
            ad += hv[d] * sWd[d*HH + o];
        }
        U[node*HH + o] = au;
        A[node*HH + o] = ad;
    }
}

// ---------------- per-node squared norm ----------------
__global__ __launch_bounds__(256) void k_sq(const float* __restrict__ h, float* __restrict__ sq)
{
    int node = blockIdx.x * 256 + threadIdx.x;
    const float4* p = (const float4*)(h + (size_t)node * HH);
    float s = 0.f;
#pragma unroll
    for (int q = 0; q < 16; q++) {
        float4 v = p[q];
        s += v.x*v.x + v.y*v.y + v.z*v.z + v.w*v.w;
    }
    sq[node] = s;
}

// ---------------- batched distance GEMM: dist[b][r][c] = sq_r + sq_c - 2*<h_r,h_c> ----------------
// grid (B, 4, 4): 128x128 tile per block, 256 threads, 8x8 per-thread register tile, f32x2 FMA.
#define DSTR 132
__global__ __launch_bounds__(256) void k_dist(const float* __restrict__ h,
                                              const float* __restrict__ sq,
                                              float* __restrict__ dist)
{
    extern __shared__ float sm2[];
    float* sA = sm2;
    float* sB = sm2 + HH*DSTR;
    int b = blockIdx.x, by = blockIdx.y, bz = blockIdx.z;
    int tid = threadIdx.x;
    const float* hb = h + ((size_t)b * NN) * HH;

    {   // load+transpose tiles: sA[d][r] (rows by*128+), sB[d][c] (cols bz*128+)
        int row = tid >> 1, half = tid & 1;
        const float4* srcA = (const float4*)(hb + (size_t)(by*128 + row)*HH + half*32);
        const float4* srcB = (const float4*)(hb + (size_t)(bz*128 + row)*HH + half*32);
#pragma unroll
        for (int q = 0; q < 8; q++) {
            int d = half*32 + q*4;
            float4 v = srcA[q];
            sA[(d+0)*DSTR+row] = v.x; sA[(d+1)*DSTR+row] = v.y;
            sA[(d+2)*DSTR+row] = v.z; sA[(d+3)*DSTR+row] = v.w;
            float4 u = srcB[q];
            sB[(d+0)*DSTR+row] = u.x; sB[(d+1)*DSTR+row] = u.y;
            sB[(d+2)*DSTR+row] = u.z; sB[(d+3)*DSTR+row] = u.w;
        }
    }
    __syncthreads();

    int tx = tid & 15, ty = tid >> 4;      // tx: 8-col group, ty: 8-row group
    ull acc[8][4];
#pragma unroll
    for (int i = 0; i < 8; i++)
#pragma unroll
        for (int m = 0; m < 4; m++) acc[i][m] = 0ull;   // bits of (0.f,0.f)

#pragma unroll 4
    for (int d = 0; d < HH; d++) {
        float4 a0 = *(const float4*)&sA[d*DSTR + ty*8];
        float4 a1 = *(const float4*)&sA[d*DSTR + ty*8 + 4];
        longlong2 q0 = *(const longlong2*)&sB[d*DSTR + tx*8];
        longlong2 q1 = *(const longlong2*)&sB[d*DSTR + tx*8 + 4];
        ull bp0 = (ull)q0.x, bp1 = (ull)q0.y, bp2 = (ull)q1.x, bp3 = (ull)q1.y;
        float ar[8] = {a0.x,a0.y,a0.z,a0.w,a1.x,a1.y,a1.z,a1.w};
#pragma unroll
        for (int i = 0; i < 8; i++) {
            ull ai = pack2(ar[i], ar[i]);
            acc[i][0] = ffma2(ai, bp0, acc[i][0]);
            acc[i][1] = ffma2(ai, bp1, acc[i][1]);
            acc[i][2] = ffma2(ai, bp2, acc[i][2]);
            acc[i][3] = ffma2(ai, bp3, acc[i][3]);
        }
    }

    int R0 = by*128 + ty*8, C0 = bz*128 + tx*8;
    float sqc[8];
#pragma unroll
    for (int j = 0; j < 8; j++) sqc[j] = sq[(b<<9) + C0 + j];

#pragma unroll
    for (int i = 0; i < 8; i++) {
        int R = R0 + i;
        float sr = sq[(b<<9) + R];
        float o[8];
#pragma unroll
        for (int m = 0; m < 4; m++) {
            float2 p = unpack2(acc[i][m]);
            o[2*m]   = fmaf(-2.f, p.x, sr + sqc[2*m]);
            o[2*m+1] = fmaf(-2.f, p.y, sr + sqc[2*m+1]);
        }
#pragma unroll
        for (int j = 0; j < 8; j++) if (R == C0 + j) o[j] = 1e30f;  // self-loop mask
        float4* dst = (float4*)&dist[((size_t)((b<<9) + R))*NN + C0];
        dst[0] = make_float4(o[0], o[1], o[2], o[3]);
        dst[1] = make_float4(o[4], o[5], o[6], o[7]);
    }
}

// ---------------- top-16 selection: warp per row, u64 keys, sort network + shfl-min merge ----------
__global__ __launch_bounds__(256) void k_sel(const float* __restrict__ dist,
                                             int* __restrict__ kn)
{
    int wid = threadIdx.x >> 5, lane = threadIdx.x & 31;
    int node = blockIdx.x * 8 + wid;
    const float* row = dist + (size_t)node * NN;

    ull key[16];
#pragma unroll
    for (int t = 0; t < 4; t++) {
        float4 v = *(const float4*)&row[lane*16 + t*4];
        float f[4] = {v.x, v.y, v.z, v.w};
#pragma unroll
        for (int q = 0; q < 4; q++) {
            int col = lane*16 + t*4 + q;
            unsigned u = __float_as_uint(f[q]);
            u = (u & 0x80000000u) ? ~u : (u | 0x80000000u);   // order-preserving flip
            key[t*4+q] = ((ull)u << 32) | (unsigned)col;       // tie -> lower index wins
        }
    }

    // Batcher odd-even mergesort, n=16, fully unrolled -> static indices
#pragma unroll
    for (int p = 1; p < 16; p <<= 1) {
#pragma unroll
        for (int k = p; k >= 1; k >>= 1) {
#pragma unroll
            for (int j = k % p; j + k < 16; j += 2*k) {
#pragma unroll
                for (int ii = 0; ii < k; ii++) {
                    int a = ii + j, c = ii + j + k;
                    if (c < 16 && (a / (2*p) == c / (2*p))) {
                        ull lo = key[a] < key[c] ? key[a] : key[c];
                        ull hi = key[a] < key[c] ? key[c] : key[a];
                        key[a] = lo; key[c] = hi;
                    }
                }
            }
        }
    }

    // 16 extraction rounds: warp-min of heads, winner shifts its sorted list
    ull head = key[0];
    int res = 0;
#pragma unroll
    for (int r = 0; r < KNN; r++) {
        ull m = head;
#pragma unroll
        for (int o = 16; o >= 1; o >>= 1) {
            ull t = __shfl_xor_sync(0xffffffffu, m, o);
            m = t < m ? t : m;
        }
        if (lane == r) res = (int)(unsigned)(m & 0xffffffffull);
        bool win = (head == m);
#pragma unroll
        for (int t = 0; t < 15; t++) key[t] = win ? key[t+1] : key[t];
        if (win) key[15] = ~0ull;
        head = key[0];
    }
    if (lane < KNN) kn[node*KNN + lane] = res;
}

// ---------------- EdgeConv per-edge: e0 = elu(A_i + U_j); h_i = sum_k elu(e0 @ W1 + b1) ----------
// warp per node, transposed e-tile [d][k] (stride 20 -> 16B-aligned pair loads), f32x2 FMA.
__global__ __launch_bounds__(128) void k_edge(const float* __restrict__ A,
                                              const float* __restrict__ U,
                                              const int* __restrict__ kn,
                                              const float* __restrict__ W1,
                                              const float* __restrict__ b1,
                                              float* __restrict__ hout)
{
    __shared__ float sW[HH*HH];
    __shared__ float sb[HH];
    __shared__ __align__(16) float e0s[4][HH][20];
    int tid = threadIdx.x;
    for (int i = tid; i < HH*HH; i += 128) sW[i] = W1[i];
    if (tid < HH) sb[tid] = b1[tid];
    __syncthreads();

    int w = tid >> 5, l = tid & 31;
    int node = blockIdx.x * 4 + w;
    int base = node & ~(NN - 1);
    float a0 = A[node*HH + l];
    float a1 = A[node*HH + l + 32];
    const int* kp = kn + node*KNN;

#pragma unroll
    for (int k = 0; k < KNN; k++) {
        int j = kp[k];
        const float* up = U + (size_t)(base + j) * HH;
        e0s[w][l][k]      = elu1(a0 + up[l]);
        e0s[w][l + 32][k] = elu1(a1 + up[l + 32]);
    }
    __syncwarp();

    ull v0[8], v1[8];
#pragma unroll
    for (int m = 0; m < 8; m++) { v0[m] = 0ull; v1[m] = 0ull; }

#pragma unroll 4
    for (int d = 0; d < HH; d++) {
        float w0 = sW[d*HH + l];
        float w1 = sW[d*HH + l + 32];
        ull w00 = pack2(w0, w0), w11 = pack2(w1, w1);
        const longlong2* ep = (const longlong2*)&e0s[w][d][0];
#pragma unroll
        for (int m = 0; m < 4; m++) {
            longlong2 q = ep[m];                 // pairs (e[4m],e[4m+1]),(e[4m+2],e[4m+3])
            v0[2*m]   = ffma2((ull)q.x, w00, v0[2*m]);
            v0[2*m+1] = ffma2((ull)q.y, w00, v0[2*m+1]);
            v1[2*m]   = ffma2((ull)q.x, w11, v1[2*m]);
            v1[2*m+1] = ffma2((ull)q.y, w11, v1[2*m+1]);
        }
    }

    float bb0 = sb[l], bb1 = sb[l + 32];
    float o0 = 0.f, o1 = 0.f;
#pragma unroll
    for (int m = 0; m < 8; m++) {
        float2 p = unpack2(v0[m]); o0 += elu1(p.x + bb0) + elu1(p.y + bb0);
        float2 r = unpack2(v1[m]); o1 += elu1(r.x + bb1) + elu1(r.y + bb1);
    }
    hout[node*HH + l]      = o0;
    hout[node*HH + l + 32] = o1;
}

// ---------------- global max-pool + output MLP + log_softmax (unchanged) ----------------
__global__ __launch_bounds__(64) void k_out(const float* __restrict__ h,
                                            const float* __restrict__ Wo0, const float* __restrict__ bo0,
                                            const float* __restrict__ Wo1, const float* __restrict__ bo1,
                                            const float* __restrict__ Wo2, const float* __restrict__ bo2,
                                            float* __restrict__ out)
{
    int b = blockIdx.x, o = threadIdx.x;
    __shared__ float s0[HH], s1[HH], slog[COUT + 1];
    const float* hb = h + (size_t)b * NN * HH;

    float m = -3.0e38f;
    for (int n = 0; n < NN; n++) m = fmaxf(m, hb[n*HH + o]);
    s0[o] = m;
    __syncthreads();

    float a = bo0[o];
    for (int d = 0; d < HH; d++) a += s0[d] * Wo0[d*HH + o];
    s1[o] = elu1(a);
    __syncthreads();

    a = bo1[o];
    for (int d = 0; d < HH; d++) a += s1[d] * Wo1[d*HH + o];
    __syncthreads();
    s0[o] = elu1(a);
    __syncthreads();

    if (o < COUT) {
        float lg = bo2[o];
        for (int d = 0; d < HH; d++) lg += s0[d] * Wo2[d*COUT + o];
        slog[o] = lg;
    }
    __syncthreads();
    if (o == 0) {
        float mx = -3.0e38f;
        for (int c = 0; c < COUT; c++) mx = fmaxf(mx, slog[c]);
        float s = 0.f;
        for (int c = 0; c < COUT; c++) s += expf(slog[c] - mx);
        slog[COUT] = mx + logf(s);
    }
    __syncthreads();
    if (o < COUT) out[b*COUT + o] = slog[o] - slog[COUT];
}

// ---------------- host launcher ----------------
extern "C" void kernel_launch(void* const* d_in, const int* in_sizes, int n_in,
                              void* d_out, int out_size)
{
    const float* x     = (const float*)d_in[0];
    const float* W_in0 = (const float*)d_in[1];
    const float* b_in0 = (const float*)d_in[2];
    const float* W_in1 = (const float*)d_in[3];
    const float* b_in1 = (const float*)d_in[4];
    const float* W_in2 = (const float*)d_in[5];
    const float* b_in2 = (const float*)d_in[6];
    const float* W_e0  = (const float*)d_in[7];
    const float* b_e0  = (const float*)d_in[8];
    const float* W_e1  = (const float*)d_in[9];
    const float* b_e1  = (const float*)d_in[10];
    const float* W_o0  = (const float*)d_in[11];
    const float* b_o0  = (const float*)d_in[12];
    const float* W_o1  = (const float*)d_in[13];
    const float* b_o1  = (const float*)d_in[14];
    const float* W_o2  = (const float*)d_in[15];
    const float* b_o2  = (const float*)d_in[16];
    float* out = (float*)d_out;

    float *h0, *h1, *A, *U, *sq, *dist;
    int* kn;
    cudaGetSymbolAddress((void**)&h0,   g_h0);
    cudaGetSymbolAddress((void**)&h1,   g_h1);
    cudaGetSymbolAddress((void**)&A,    g_A);
    cudaGetSymbolAddress((void**)&U,    g_U);
    cudaGetSymbolAddress((void**)&sq,   g_sq);
    cudaGetSymbolAddress((void**)&dist, g_dist);
    cudaGetSymbolAddress((void**)&kn,   g_knn);

    const int dist_smem = 2 * HH * DSTR * sizeof(float);
    cudaFuncSetAttribute(k_dist, cudaFuncAttributeMaxDynamicSharedMemorySize, dist_smem);

    // input MLP: x -> h1 -> A -> h0
    k_lin<FIN><<<NODES/256, 256>>>(x,  W_in0, b_in0, h1);
    k_lin<HH> <<<NODES/256, 256>>>(h1, W_in1, b_in1, A);
    k_lin<HH> <<<NODES/256, 256>>>(A,  W_in2, b_in2, h0);

    // 2 dynamic-kNN EdgeConv layers: h0 -> h1 -> h0
    for (int l = 0; l < 2; l++) {
        const float* hin  = (l == 0) ? h0 : h1;
        float*       hout = (l == 0) ? h1 : h0;
        k_sq  <<<NODES/256, 256>>>(hin, sq);
        dim3 dg(BB, 4, 4);
        k_dist<<<dg, 256, dist_smem>>>(hin, sq, dist);
        k_sel <<<NODES/8, 256>>>(dist, kn);
        k_pre <<<NODES/256, 256>>>(hin, W_e0 + (size_t)l*2*HH*HH, b_e0 + l*HH, A, U);
        k_edge<<<NODES/4, 128>>>(A, U, kn, W_e1 + (size_t)l*HH*HH, b_e1 + l*HH, hout);
    }

    k_out<<<BB, 64>>>(h0, W_o0, b_o0, W_o1, b_o1, W_o2, b_o2, out);
}

// round 5
// speedup vs baseline: 1.0789x; 1.0789x over previous
#include <cuda_runtime.h>
#include <math.h>

#define BB   128
#define NN   512
#define FIN  5
#define HH   64
#define KNN  16
#define COUT 10
#define NODES (BB*NN)
#define HTS  520   // hT row stride in floats ([d][col], 512 cols + pad)

typedef unsigned long long ull;

// ---------------- scratch (device globals: no allocation allowed) ----------------
__device__ float g_h0[NODES*HH];
__device__ float g_h1[NODES*HH];
__device__ float g_A [NODES*HH];
__device__ float g_U [NODES*HH];
__device__ int   g_knn[NODES*KNN];

__device__ __forceinline__ float elu1(float x) { return x > 0.f ? x : expm1f(x); }

// ---- packed f32x2 helpers (Blackwell FFMA2 via PTX) ----
__device__ __forceinline__ ull pack2(float x, float y) {
    ull r; asm("mov.b64 %0, {%1,%2};" : "=l"(r) : "f"(x), "f"(y)); return r;
}
__device__ __forceinline__ float2 unpack2(ull v) {
    float2 f; asm("mov.b64 {%0,%1}, %2;" : "=f"(f.x), "=f"(f.y) : "l"(v)); return f;
}
__device__ __forceinline__ ull ffma2(ull a, ull b, ull c) {
    ull d; asm("fma.rn.f32x2 %0, %1, %2, %3;" : "=l"(d) : "l"(a), "l"(b), "l"(c)); return d;
}

// order-preserving float->uint flip (ascending float order == ascending uint order)
__device__ __forceinline__ unsigned fflip(float f) {
    unsigned u = __float_as_uint(f);
    return ((int)u < 0) ? ~u : (u | 0x80000000u);
}

// Batcher odd-even mergesort, n=16, in-register, fully unrolled
__device__ __forceinline__ void sort16(ull key[16]) {
#pragma unroll
    for (int p = 1; p < 16; p <<= 1) {
#pragma unroll
        for (int k = p; k >= 1; k >>= 1) {
#pragma unroll
            for (int j = k % p; j + k < 16; j += 2*k) {
#pragma unroll
                for (int ii = 0; ii < k; ii++) {
                    int a = ii + j, c = ii + j + k;
                    if (c < 16 && (a / (2*p) == c / (2*p))) {
                        ull lo = key[a] < key[c] ? key[a] : key[c];
                        ull hi = key[a] < key[c] ? key[c] : key[a];
                        key[a] = lo; key[c] = hi;
                    }
                }
            }
        }
    }
}

// ---------------- generic per-node GEMV + ELU ----------------
template<int IN>
__global__ __launch_bounds__(256) void k_lin(const float* __restrict__ in,
                                             const float* __restrict__ W,
                                             const float* __restrict__ b,
                                             float* __restrict__ out)
{
    __shared__ float sW[IN*HH];
    __shared__ float sb[HH];
    int tid = threadIdx.x;
    for (int i = tid; i < IN*HH; i += 256) sW[i] = W[i];
    if (tid < HH) sb[tid] = b[tid];
    __syncthreads();

    int node = blockIdx.x * 256 + tid;
    float v[IN];
#pragma unroll
    for (int d = 0; d < IN; d++) v[d] = in[node*IN + d];

    for (int o = 0; o < HH; o++) {
        float a = sb[o];
#pragma unroll
        for (int d = 0; d < IN; d++) a += v[d] * sW[d*HH + o];
        out[node*HH + o] = elu1(a);
    }
}

// ---------------- EdgeConv layer-0 factorization ----------------
__global__ __launch_bounds__(256) void k_pre(const float* __restrict__ h,
                                             const float* __restrict__ W0,
                                             const float* __restrict__ b0,
                                             float* __restrict__ A,
                                             float* __restrict__ U)
{
    __shared__ float sWb[HH*HH];
    __shared__ float sWd[HH*HH];
    __shared__ float sb[HH];
    int tid = threadIdx.x;
    for (int i = tid; i < HH*HH; i += 256) {
        float wa = W0[i];
        float wb = W0[HH*HH + i];
        sWb[i] = wb;
        sWd[i] = wa - wb;
    }
    if (tid < HH) sb[tid] = b0[tid];
    __syncthreads();

    int node = blockIdx.x * 256 + tid;
    float hv[HH];
#pragma unroll
    for (int d = 0; d < HH; d++) hv[d] = h[node*HH + d];

    for (int o = 0; o < HH; o++) {
        float au = 0.f, ad = sb[o];
#pragma unroll
        for (int d = 0; d < HH; d++) {
            au += hv[d] * sWb[d*HH + o];
            ad += hv[d] * sWd[d*HH + o];
        }
        U[node*HH + o] = au;
        A[node*HH + o] = ad;
    }
}

// ---------------- fused kNN: per-batch block, warp-per-row distance + exact top-16 ----------------
// smem: hT[64][HTS] transposed features (133KB) + sq[512] (2KB) + sel[16 warps][16 slots][32 lanes] u64 (64KB)
__global__ __launch_bounds__(512) void k_knn2(const float* __restrict__ h,
                                              int* __restrict__ kn)
{
    extern __shared__ __align__(16) char smraw[];
    float* hT = (float*)smraw;                 // [64][HTS]
    float* sq = hT + HH*HTS;                   // [512]
    ull*   sel = (ull*)(sq + NN);              // [16][16][32]

    int b = blockIdx.x, tid = threadIdx.x;
    int w = tid >> 5, lane = tid & 31;
    const float* hb = h + (size_t)b * NN * HH;

    // load + transpose (thread per column) and fold in squared-norm computation
    {
        const float4* src = (const float4*)(hb + (size_t)tid * HH);
        float s = 0.f;
#pragma unroll
        for (int q = 0; q < 16; q++) {
            float4 v = src[q];
            int d = q * 4;
            hT[(d+0)*HTS + tid] = v.x;
            hT[(d+1)*HTS + tid] = v.y;
            hT[(d+2)*HTS + tid] = v.z;
            hT[(d+3)*HTS + tid] = v.w;
            s += v.x*v.x + v.y*v.y + v.z*v.z + v.w*v.w;
        }
        sq[tid] = s;
    }
    __syncthreads();

    ull* wsel = sel + w * 16 * 32;

    // 16 passes x 2 rows per warp = 32 rows/warp, 512 rows/block
#pragma unroll 1
    for (int rr = 0; rr < 16; rr++) {
        int i0 = rr*32 + w*2;
        int i1 = i0 + 1;

        ull acc0[8], acc1[8];
#pragma unroll
        for (int t = 0; t < 8; t++) { acc0[t] = 0ull; acc1[t] = 0ull; }

#pragma unroll 4
        for (int d = 0; d < HH; d++) {
            const float* rowp = hT + d*HTS;
            float x0 = rowp[i0], x1 = rowp[i1];        // warp-uniform broadcasts
            ull x0p = pack2(x0, x0), x1p = pack2(x1, x1);
            const ull* bp = (const ull*)rowp;           // col pairs (2p, 2p+1)
#pragma unroll
            for (int t = 0; t < 8; t++) {
                ull bv = bp[lane + 32*t];
                acc0[t] = ffma2(x0p, bv, acc0[t]);
                acc1[t] = ffma2(x1p, bv, acc1[t]);
            }
        }

        // per-row: build keys -> sort16 -> spill sorted list -> 16x warp-min merge
#pragma unroll 1
        for (int r = 0; r < 2; r++) {
            int i = r ? i1 : i0;
            float sqi = sq[i];
            ull key[16];
#pragma unroll
            for (int t = 0; t < 8; t++) {
                int p = lane + 32*t;
                float2 dp = unpack2(r ? acc1[t] : acc0[t]);
                float2 sp = ((const float2*)sq)[p];
                float d0 = fmaf(-2.f, dp.x, sqi + sp.x);
                float d1 = fmaf(-2.f, dp.y, sqi + sp.y);
                int c0 = 2*p, c1 = 2*p + 1;
                key[2*t]   = (c0 == i) ? ~0ull : (((ull)fflip(d0) << 32) | (unsigned)c0);
                key[2*t+1] = (c1 == i) ? ~0ull : (((ull)fflip(d1) << 32) | (unsigned)c1);
            }

            sort16(key);

#pragma unroll
            for (int s = 0; s < 16; s++) wsel[s*32 + lane] = key[s];
            __syncwarp();

            ull head = key[0];
            int ptr = 0, res = 0;
#pragma unroll
            for (int rd = 0; rd < KNN; rd++) {
                ull m = head;
#pragma unroll
                for (int o = 16; o >= 1; o >>= 1) {
                    ull t = __shfl_xor_sync(0xffffffffu, m, o);
                    m = t < m ? t : m;
                }
                if (lane == rd) res = (int)(unsigned)(m & 0xffffffffull);
                if (head == m) {                 // keys unique (col in low bits) -> one winner
                    ptr++;
                    head = (ptr < 16) ? wsel[ptr*32 + lane] : ~0ull;
                }
            }
            if (lane < KNN) kn[((size_t)b*NN + i)*KNN + lane] = res;
            __syncwarp();
        }
    }
}

// ---------------- EdgeConv per-edge: 16 nodes/block (warp per node), f32x2 FMA ----------------
__global__ __launch_bounds__(512) void k_edge(const float* __restrict__ A,
                                              const float* __restrict__ U,
                                              const int* __restrict__ kn,
                                              const float* __restrict__ W1,
                                              const float* __restrict__ b1,
                                              float* __restrict__ hout)
{
    extern __shared__ __align__(16) char esm[];
    float* sW  = (float*)esm;                      // [64*64]
    float* sb  = sW + HH*HH;                       // [64]
    float* e0s = sb + HH;                          // [16][64][20]

    int tid = threadIdx.x;
    for (int i = tid; i < HH*HH; i += 512) sW[i] = W1[i];
    if (tid < HH) sb[tid] = b1[tid];
    __syncthreads();

    int w = tid >> 5, l = tid & 31;
    int node = blockIdx.x * 16 + w;
    int base = node & ~(NN - 1);
    float a0 = A[node*HH + l];
    float a1 = A[node*HH + l + 32];
    const int* kp = kn + node*KNN;
    float* e0w = e0s + w * (HH*20);

#pragma unroll
    for (int k = 0; k < KNN; k++) {
        int j = kp[k];
        const float* up = U + (size_t)(base + j) * HH;
        e0w[l*20 + k]        = elu1(a0 + up[l]);
        e0w[(l+32)*20 + k]   = elu1(a1 + up[l + 32]);
    }
    __syncwarp();

    ull v0[8], v1[8];
#pragma unroll
    for (int m = 0; m < 8; m++) { v0[m] = 0ull; v1[m] = 0ull; }

#pragma unroll 4
    for (int d = 0; d < HH; d++) {
        float w0 = sW[d*HH + l];
        float w1 = sW[d*HH + l + 32];
        ull w00 = pack2(w0, w0), w11 = pack2(w1, w1);
        const longlong2* ep = (const longlong2*)&e0w[d*20];
#pragma unroll
        for (int m = 0; m < 4; m++) {
            longlong2 q = ep[m];
            v0[2*m]   = ffma2((ull)q.x, w00, v0[2*m]);
            v0[2*m+1] = ffma2((ull)q.y, w00, v0[2*m+1]);
            v1[2*m]   = ffma2((ull)q.x, w11, v1[2*m]);
            v1[2*m+1] = ffma2((ull)q.y, w11, v1[2*m+1]);
        }
    }

    float bb0 = sb[l], bb1 = sb[l + 32];
    float o0 = 0.f, o1 = 0.f;
#pragma unroll
    for (int m = 0; m < 8; m++) {
        float2 p = unpack2(v0[m]); o0 += elu1(p.x + bb0) + elu1(p.y + bb0);
        float2 r = unpack2(v1[m]); o1 += elu1(r.x + bb1) + elu1(r.y + bb1);
    }
    hout[node*HH + l]      = o0;
    hout[node*HH + l + 32] = o1;
}

// ---------------- global max-pool + output MLP + log_softmax ----------------
__global__ __launch_bounds__(64) void k_out(const float* __restrict__ h,
                                            const float* __restrict__ Wo0, const float* __restrict__ bo0,
                                            const float* __restrict__ Wo1, const float* __restrict__ bo1,
                                            const float* __restrict__ Wo2, const float* __restrict__ bo2,
                                            float* __restrict__ out)
{
    int b = blockIdx.x, o = threadIdx.x;
    __shared__ float s0[HH], s1[HH], slog[COUT + 1];
    const float* hb = h + (size_t)b * NN * HH;

    float m = -3.0e38f;
    for (int n = 0; n < NN; n++) m = fmaxf(m, hb[n*HH + o]);
    s0[o] = m;
    __syncthreads();

    float a = bo0[o];
    for (int d = 0; d < HH; d++) a += s0[d] * Wo0[d*HH + o];
    s1[o] = elu1(a);
    __syncthreads();

    a = bo1[o];
    for (int d = 0; d < HH; d++) a += s1[d] * Wo1[d*HH + o];
    __syncthreads();
    s0[o] = elu1(a);
    __syncthreads();

    if (o < COUT) {
        float lg = bo2[o];
        for (int d = 0; d < HH; d++) lg += s0[d] * Wo2[d*COUT + o];
        slog[o] = lg;
    }
    __syncthreads();
    if (o == 0) {
        float mx = -3.0e38f;
        for (int c = 0; c < COUT; c++) mx = fmaxf(mx, slog[c]);
        float s = 0.f;
        for (int c = 0; c < COUT; c++) s += expf(slog[c] - mx);
        slog[COUT] = mx + logf(s);
    }
    __syncthreads();
    if (o < COUT) out[b*COUT + o] = slog[o] - slog[COUT];
}

// ---------------- host launcher ----------------
extern "C" void kernel_launch(void* const* d_in, const int* in_sizes, int n_in,
                              void* d_out, int out_size)
{
    const float* x     = (const float*)d_in[0];
    const float* W_in0 = (const float*)d_in[1];
    const float* b_in0 = (const float*)d_in[2];
    const float* W_in1 = (const float*)d_in[3];
    const float* b_in1 = (const float*)d_in[4];
    const float* W_in2 = (const float*)d_in[5];
    const float* b_in2 = (const float*)d_in[6];
    const float* W_e0  = (const float*)d_in[7];
    const float* b_e0  = (const float*)d_in[8];
    const float* W_e1  = (const float*)d_in[9];
    const float* b_e1  = (const float*)d_in[10];
    const float* W_o0  = (const float*)d_in[11];
    const float* b_o0  = (const float*)d_in[12];
    const float* W_o1  = (const float*)d_in[13];
    const float* b_o1  = (const float*)d_in[14];
    const float* W_o2  = (const float*)d_in[15];
    const float* b_o2  = (const float*)d_in[16];
    float* out = (float*)d_out;

    float *h0, *h1, *A, *U;
    int* kn;
    cudaGetSymbolAddress((void**)&h0, g_h0);
    cudaGetSymbolAddress((void**)&h1, g_h1);
    cudaGetSymbolAddress((void**)&A,  g_A);
    cudaGetSymbolAddress((void**)&U,  g_U);
    cudaGetSymbolAddress((void**)&kn, g_knn);

    const int knn_smem  = (HH*HTS + NN) * sizeof(float) + 16*16*32*sizeof(ull); // 133KB+2KB+64KB
    const int edge_smem = (HH*HH + HH + 16*HH*20) * sizeof(float);              // ~98.6KB
    cudaFuncSetAttribute(k_knn2, cudaFuncAttributeMaxDynamicSharedMemorySize, knn_smem);
    cudaFuncSetAttribute(k_edge, cudaFuncAttributeMaxDynamicSharedMemorySize, edge_smem);

    // input MLP: x -> h1 -> A -> h0
    k_lin<FIN><<<NODES/256, 256>>>(x,  W_in0, b_in0, h1);
    k_lin<HH> <<<NODES/256, 256>>>(h1, W_in1, b_in1, A);
    k_lin<HH> <<<NODES/256, 256>>>(A,  W_in2, b_in2, h0);

    // 2 dynamic-kNN EdgeConv layers: h0 -> h1 -> h0
    for (int l = 0; l < 2; l++) {
        const float* hin  = (l == 0) ? h0 : h1;
        float*       hout = (l == 0) ? h1 : h0;
        k_knn2<<<BB, 512, knn_smem>>>(hin, kn);
        k_pre <<<NODES/256, 256>>>(hin, W_e0 + (size_t)l*2*HH*HH, b_e0 + l*HH, A, U);
        k_edge<<<NODES/16, 512, edge_smem>>>(A, U, kn, W_e1 + (size_t)l*HH*HH, b_e1 + l*HH, hout);
    }

    k_out<<<BB, 64>>>(h0, W_o0, b_o0, W_o1, b_o1, W_o2, b_o2, out);
}

// round 6
// speedup vs baseline: 1.2170x; 1.1281x over previous
#include <cuda_runtime.h>
#include <math.h>

#define BB   128
#define NN   512
#define FIN  5
#define HH   64
#define KNN  16
#define COUT 10
#define NODES (BB*NN)
#define HTS  520   // hT row stride in floats ([d][col], 512 cols + pad)

typedef unsigned long long ull;

// ---------------- scratch (device globals: no allocation allowed) ----------------
__device__ float g_h0[NODES*HH];
__device__ float g_h1[NODES*HH];
__device__ float g_A [NODES*HH];
__device__ float g_U [NODES*HH];
__device__ int   g_knn[NODES*KNN];

__device__ __forceinline__ float elu1(float x) { return x > 0.f ? x : expm1f(x); }

// ---- packed f32x2 helpers (Blackwell FFMA2 via PTX) ----
__device__ __forceinline__ ull pack2(float x, float y) {
    ull r; asm("mov.b64 %0, {%1,%2};" : "=l"(r) : "f"(x), "f"(y)); return r;
}
__device__ __forceinline__ float2 unpack2(ull v) {
    float2 f; asm("mov.b64 {%0,%1}, %2;" : "=f"(f.x), "=f"(f.y) : "l"(v)); return f;
}
__device__ __forceinline__ ull ffma2(ull a, ull b, ull c) {
    ull d; asm("fma.rn.f32x2 %0, %1, %2, %3;" : "=l"(d) : "l"(a), "l"(b), "l"(c)); return d;
}

// order-preserving float->uint flip
__device__ __forceinline__ unsigned fflip(float f) {
    unsigned u = __float_as_uint(f);
    return ((int)u < 0) ? ~u : (u | 0x80000000u);
}

// Batcher odd-even mergesort, n=16, in-register, fully unrolled
__device__ __forceinline__ void sort16(ull key[16]) {
#pragma unroll
    for (int p = 1; p < 16; p <<= 1) {
#pragma unroll
        for (int k = p; k >= 1; k >>= 1) {
#pragma unroll
            for (int j = k % p; j + k < 16; j += 2*k) {
#pragma unroll
                for (int ii = 0; ii < k; ii++) {
                    int a = ii + j, c = ii + j + k;
                    if (c < 16 && (a / (2*p) == c / (2*p))) {
                        ull lo = key[a] < key[c] ? key[a] : key[c];
                        ull hi = key[a] < key[c] ? key[c] : key[a];
                        key[a] = lo; key[c] = hi;
                    }
                }
            }
        }
    }
}

// ---------------- input layer 0 (IN=5, scalar) ----------------
__global__ __launch_bounds__(256) void k_lin5(const float* __restrict__ in,
                                              const float* __restrict__ W,
                                              const float* __restrict__ b,
                                              float* __restrict__ out)
{
    __shared__ float sW[FIN*HH];
    __shared__ float sb[HH];
    int tid = threadIdx.x;
    for (int i = tid; i < FIN*HH; i += 256) sW[i] = W[i];
    if (tid < HH) sb[tid] = b[tid];
    __syncthreads();

    int node = blockIdx.x * 256 + tid;
    float v[FIN];
#pragma unroll
    for (int d = 0; d < FIN; d++) v[d] = in[node*FIN + d];

    for (int o = 0; o < HH; o++) {
        float a = sb[o];
#pragma unroll
        for (int d = 0; d < FIN; d++) a += v[d] * sW[d*HH + o];
        out[node*HH + o] = elu1(a);
    }
}

// ---------------- 64x64 GEMV + ELU, f32x2 packed output pairs ----------------
__global__ __launch_bounds__(256) void k_lin64(const float* __restrict__ in,
                                               const float* __restrict__ W,
                                               const float* __restrict__ b,
                                               float* __restrict__ out)
{
    __shared__ __align__(16) float sW[HH*HH];
    __shared__ float sb[HH];
    int tid = threadIdx.x;
    for (int i = tid; i < HH*HH; i += 256) sW[i] = W[i];
    if (tid < HH) sb[tid] = b[tid];
    __syncthreads();

    int node = blockIdx.x * 256 + tid;
    float v[HH];
#pragma unroll
    for (int d = 0; d < HH; d++) v[d] = in[node*HH + d];

#pragma unroll 2
    for (int op = 0; op < 32; op++) {
        ull acc = 0ull;
#pragma unroll
        for (int d = 0; d < HH; d++) {
            ull hp = pack2(v[d], v[d]);
            ull wv = ((const ull*)(sW + d*HH))[op];   // broadcast LDS.64
            acc = ffma2(hp, wv, acc);
        }
        float2 p = unpack2(acc);
        float2 o2 = make_float2(elu1(p.x + sb[2*op]), elu1(p.y + sb[2*op+1]));
        *(float2*)&out[node*HH + 2*op] = o2;
    }
}

// ---------------- EdgeConv layer-0 factorization, packed ----------------
__global__ __launch_bounds__(256) void k_pre(const float* __restrict__ h,
                                             const float* __restrict__ W0,
                                             const float* __restrict__ b0,
                                             float* __restrict__ A,
                                             float* __restrict__ U)
{
    __shared__ __align__(16) float sWb[HH*HH];
    __shared__ __align__(16) float sWd[HH*HH];
    __shared__ float sb[HH];
    int tid = threadIdx.x;
    for (int i = tid; i < HH*HH; i += 256) {
        float wa = W0[i];
        float wb = W0[HH*HH + i];
        sWb[i] = wb;
        sWd[i] = wa - wb;
    }
    if (tid < HH) sb[tid] = b0[tid];
    __syncthreads();

    int node = blockIdx.x * 256 + tid;
    float hv[HH];
#pragma unroll
    for (int d = 0; d < HH; d++) hv[d] = h[node*HH + d];

#pragma unroll 2
    for (int op = 0; op < 32; op++) {
        ull au = 0ull, ad = 0ull;
#pragma unroll
        for (int d = 0; d < HH; d++) {
            ull hp = pack2(hv[d], hv[d]);
            au = ffma2(hp, ((const ull*)(sWb + d*HH))[op], au);
            ad = ffma2(hp, ((const ull*)(sWd + d*HH))[op], ad);
        }
        float2 pu = unpack2(au);
        *(float2*)&U[node*HH + 2*op] = pu;
        float2 pa = unpack2(ad);
        pa.x += sb[2*op]; pa.y += sb[2*op+1];
        *(float2*)&A[node*HH + 2*op] = pa;
    }
}

// ---------------- fused kNN: per-batch block, 4 rows/warp tiling + REDUX top-16 ----------------
// smem: hT[64][HTS] (133KB) + sq[512] (2KB) + sel[16 warps][16][32] ull (64KB) = ~196KB
__global__ __launch_bounds__(512) void k_knn2(const float* __restrict__ h,
                                              int* __restrict__ kn)
{
    extern __shared__ __align__(16) char smraw[];
    float* hT = (float*)smraw;                 // [64][HTS]
    float* sq = hT + HH*HTS;                   // [512]
    ull*   sel = (ull*)(sq + NN);              // [16][16][32]

    int b = blockIdx.x, tid = threadIdx.x;
    int w = tid >> 5, lane = tid & 31;
    const float* hb = h + (size_t)b * NN * HH;

    // load + transpose (thread per column), fold in squared norms
    {
        const float4* src = (const float4*)(hb + (size_t)tid * HH);
        float s = 0.f;
#pragma unroll
        for (int q = 0; q < 16; q++) {
            float4 v = src[q];
            int d = q * 4;
            hT[(d+0)*HTS + tid] = v.x;
            hT[(d+1)*HTS + tid] = v.y;
            hT[(d+2)*HTS + tid] = v.z;
            hT[(d+3)*HTS + tid] = v.w;
            s += v.x*v.x + v.y*v.y + v.z*v.z + v.w*v.w;
        }
        sq[tid] = s;
    }
    __syncthreads();

    ull* wsel = sel + w * 16 * 32;

    // 8 passes x 4 rows per warp = 32 rows/warp, 512 rows/block
#pragma unroll 1
    for (int pp = 0; pp < 8; pp++) {
        int i0 = pp*64 + w*4;                  // 4 consecutive rows, 16B aligned in hT

        ull acc[4][8];
#pragma unroll
        for (int r = 0; r < 4; r++)
#pragma unroll
            for (int t = 0; t < 8; t++) acc[r][t] = 0ull;

#pragma unroll 4
        for (int d = 0; d < HH; d++) {
            const float* rowp = hT + d*HTS;
            float4 xv = *(const float4*)(rowp + i0);   // broadcast LDS.128
            ull xp0 = pack2(xv.x, xv.x), xp1 = pack2(xv.y, xv.y);
            ull xp2 = pack2(xv.z, xv.z), xp3 = pack2(xv.w, xv.w);
            const ull* bp = (const ull*)rowp;
#pragma unroll
            for (int t = 0; t < 8; t++) {
                ull bv = bp[lane + 32*t];
                acc[0][t] = ffma2(xp0, bv, acc[0][t]);
                acc[1][t] = ffma2(xp1, bv, acc[1][t]);
                acc[2][t] = ffma2(xp2, bv, acc[2][t]);
                acc[3][t] = ffma2(xp3, bv, acc[3][t]);
            }
        }

        // per-row: keys -> sort16 -> spill sorted list -> 16x REDUX-min merge
#pragma unroll 1
        for (int r = 0; r < 4; r++) {
            int i = i0 + r;
            float sqi = sq[i];
            ull key[16];
#pragma unroll
            for (int t = 0; t < 8; t++) {
                int p = lane + 32*t;
                float2 dp = unpack2(acc[r][t]);
                float2 sp = ((const float2*)sq)[p];
                float d0 = fmaf(-2.f, dp.x, sqi + sp.x);
                float d1 = fmaf(-2.f, dp.y, sqi + sp.y);
                int c0 = 2*p, c1 = 2*p + 1;
                key[2*t]   = (c0 == i) ? ~0ull : (((ull)fflip(d0) << 32) | (unsigned)c0);
                key[2*t+1] = (c1 == i) ? ~0ull : (((ull)fflip(d1) << 32) | (unsigned)c1);
            }

            sort16(key);

#pragma unroll
            for (int s = 0; s < 16; s++) wsel[s*32 + lane] = key[s];
            __syncwarp();

            ull head = key[0];
            int ptr = 0, res = 0;
#pragma unroll
            for (int rd = 0; rd < KNN; rd++) {
                unsigned hi  = (unsigned)(head >> 32);
                unsigned mhi = __reduce_min_sync(0xffffffffu, hi);
                unsigned lo  = (hi == mhi) ? (unsigned)head : 0xffffffffu;
                unsigned mlo = __reduce_min_sync(0xffffffffu, lo);
                if (lane == rd) res = (int)mlo;            // low 32 bits == column index
                bool win = (hi == mhi) & ((unsigned)head == mlo);  // unique keys -> one winner
                if (win) {
                    ptr++;
                    head = (ptr < 16) ? wsel[ptr*32 + lane] : ~0ull;
                }
            }
            if (lane < KNN) kn[((size_t)b*NN + i)*KNN + lane] = res;
            __syncwarp();
        }
    }
}

// ---------------- EdgeConv per-edge: 2 nodes/warp, 16 nodes/block, f32x2 FMA ----------------
__global__ __launch_bounds__(256) void k_edge(const float* __restrict__ A,
                                              const float* __restrict__ U,
                                              const int* __restrict__ kn,
                                              const float* __restrict__ W1,
                                              const float* __restrict__ b1,
                                              float* __restrict__ hout)
{
    extern __shared__ __align__(16) char esm[];
    float* sW  = (float*)esm;                      // [64*64]
    float* sb  = sW + HH*HH;                       // [64]
    float* e0s = sb + HH;                          // [16 nodes][64][20]

    int tid = threadIdx.x;
    for (int i = tid; i < HH*HH; i += 256) sW[i] = W1[i];
    if (tid < HH) sb[tid] = b1[tid];
    __syncthreads();

    int w = tid >> 5, l = tid & 31;
    int n0 = blockIdx.x * 16 + w*2;
    int n1 = n0 + 1;
    int base = n0 & ~(NN - 1);
    float a00 = A[n0*HH + l],  a01 = A[n0*HH + l + 32];
    float a10 = A[n1*HH + l],  a11 = A[n1*HH + l + 32];
    const int* kp0 = kn + n0*KNN;
    const int* kp1 = kn + n1*KNN;
    float* e0 = e0s + (size_t)(w*2)   * (HH*20);
    float* e1 = e0s + (size_t)(w*2+1) * (HH*20);

#pragma unroll
    for (int k = 0; k < KNN; k++) {
        const float* up0 = U + (size_t)(base + kp0[k]) * HH;
        e0[l*20 + k]      = elu1(a00 + up0[l]);
        e0[(l+32)*20 + k] = elu1(a01 + up0[l + 32]);
        const float* up1 = U + (size_t)(base + kp1[k]) * HH;
        e1[l*20 + k]      = elu1(a10 + up1[l]);
        e1[(l+32)*20 + k] = elu1(a11 + up1[l + 32]);
    }
    __syncwarp();

    ull v0a[8], v0b[8], v1a[8], v1b[8];
#pragma unroll
    for (int m = 0; m < 8; m++) { v0a[m]=0ull; v0b[m]=0ull; v1a[m]=0ull; v1b[m]=0ull; }

#pragma unroll 4
    for (int d = 0; d < HH; d++) {
        float w0 = sW[d*HH + l];
        float w1 = sW[d*HH + l + 32];
        ull w00 = pack2(w0, w0), w11 = pack2(w1, w1);
        const longlong2* ep0 = (const longlong2*)&e0[d*20];
        const longlong2* ep1 = (const longlong2*)&e1[d*20];
#pragma unroll
        for (int m = 0; m < 4; m++) {
            longlong2 q0 = ep0[m];
            v0a[2*m]   = ffma2((ull)q0.x, w00, v0a[2*m]);
            v0a[2*m+1] = ffma2((ull)q0.y, w00, v0a[2*m+1]);
            v0b[2*m]   = ffma2((ull)q0.x, w11, v0b[2*m]);
            v0b[2*m+1] = ffma2((ull)q0.y, w11, v0b[2*m+1]);
            longlong2 q1 = ep1[m];
            v1a[2*m]   = ffma2((ull)q1.x, w00, v1a[2*m]);
            v1a[2*m+1] = ffma2((ull)q1.y, w00, v1a[2*m+1]);
            v1b[2*m]   = ffma2((ull)q1.x, w11, v1b[2*m]);
            v1b[2*m+1] = ffma2((ull)q1.y, w11, v1b[2*m+1]);
        }
    }

    float bb0 = sb[l], bb1 = sb[l + 32];
    float o0a = 0.f, o0b = 0.f, o1a = 0.f, o1b = 0.f;
#pragma unroll
    for (int m = 0; m < 8; m++) {
        float2 p;
        p = unpack2(v0a[m]); o0a += elu1(p.x + bb0) + elu1(p.y + bb0);
        p = unpack2(v0b[m]); o0b += elu1(p.x + bb1) + elu1(p.y + bb1);
        p = unpack2(v1a[m]); o1a += elu1(p.x + bb0) + elu1(p.y + bb0);
        p = unpack2(v1b[m]); o1b += elu1(p.x + bb1) + elu1(p.y + bb1);
    }
    hout[n0*HH + l]      = o0a;
    hout[n0*HH + l + 32] = o0b;
    hout[n1*HH + l]      = o1a;
    hout[n1*HH + l + 32] = o1b;
}

// ---------------- global max-pool + output MLP + log_softmax ----------------
__global__ __launch_bounds__(64) void k_out(const float* __restrict__ h,
                                            const float* __restrict__ Wo0, const float* __restrict__ bo0,
                                            const float* __restrict__ Wo1, const float* __restrict__ bo1,
                                            const float* __restrict__ Wo2, const float* __restrict__ bo2,
                                            float* __restrict__ out)
{
    int b = blockIdx.x, o = threadIdx.x;
    __shared__ float s0[HH], s1[HH], slog[COUT + 1];
    const float* hb = h + (size_t)b * NN * HH;

    float m = -3.0e38f;
    for (int n = 0; n < NN; n++) m = fmaxf(m, hb[n*HH + o]);
    s0[o] = m;
    __syncthreads();

    float a = bo0[o];
    for (int d = 0; d < HH; d++) a += s0[d] * Wo0[d*HH + o];
    s1[o] = elu1(a);
    __syncthreads();

    a = bo1[o];
    for (int d = 0; d < HH; d++) a += s1[d] * Wo1[d*HH + o];
    __syncthreads();
    s0[o] = elu1(a);
    __syncthreads();

    if (o < COUT) {
        float lg = bo2[o];
        for (int d = 0; d < HH; d++) lg += s0[d] * Wo2[d*COUT + o];
        slog[o] = lg;
    }
    __syncthreads();
    if (o == 0) {
        float mx = -3.0e38f;
        for (int c = 0; c < COUT; c++) mx = fmaxf(mx, slog[c]);
        float s = 0.f;
        for (int c = 0; c < COUT; c++) s += expf(slog[c] - mx);
        slog[COUT] = mx + logf(s);
    }
    __syncthreads();
    if (o < COUT) out[b*COUT + o] = slog[o] - slog[COUT];
}

// ---------------- host launcher ----------------
extern "C" void kernel_launch(void* const* d_in, const int* in_sizes, int n_in,
                              void* d_out, int out_size)
{
    const float* x     = (const float*)d_in[0];
    const float* W_in0 = (const float*)d_in[1];
    const float* b_in0 = (const float*)d_in[2];
    const float* W_in1 = (const float*)d_in[3];
    const float* b_in1 = (const float*)d_in[4];
    const float* W_in2 = (const float*)d_in[5];
    const float* b_in2 = (const float*)d_in[6];
    const float* W_e0  = (const float*)d_in[7];
    const float* b_e0  = (const float*)d_in[8];
    const float* W_e1  = (const float*)d_in[9];
    const float* b_e1  = (const float*)d_in[10];
    const float* W_o0  = (const float*)d_in[11];
    const float* b_o0  = (const float*)d_in[12];
    const float* W_o1  = (const float*)d_in[13];
    const float* b_o1  = (const float*)d_in[14];
    const float* W_o2  = (const float*)d_in[15];
    const float* b_o2  = (const float*)d_in[16];
    float* out = (float*)d_out;

    float *h0, *h1, *A, *U;
    int* kn;
    cudaGetSymbolAddress((void**)&h0, g_h0);
    cudaGetSymbolAddress((void**)&h1, g_h1);
    cudaGetSymbolAddress((void**)&A,  g_A);
    cudaGetSymbolAddress((void**)&U,  g_U);
    cudaGetSymbolAddress((void**)&kn, g_knn);

    const int knn_smem  = (HH*HTS + NN) * sizeof(float) + 16*16*32*sizeof(ull); // ~196KB
    const int edge_smem = (HH*HH + HH + 16*HH*20) * sizeof(float);              // ~98.6KB
    cudaFuncSetAttribute(k_knn2, cudaFuncAttributeMaxDynamicSharedMemorySize, knn_smem);
    cudaFuncSetAttribute(k_edge, cudaFuncAttributeMaxDynamicSharedMemorySize, edge_smem);

    // input MLP: x -> h1 -> A -> h0
    k_lin5 <<<NODES/256, 256>>>(x,  W_in0, b_in0, h1);
    k_lin64<<<NODES/256, 256>>>(h1, W_in1, b_in1, A);
    k_lin64<<<NODES/256, 256>>>(A,  W_in2, b_in2, h0);

    // 2 dynamic-kNN EdgeConv layers: h0 -> h1 -> h0
    for (int l = 0; l < 2; l++) {
        const float* hin  = (l == 0) ? h0 : h1;
        float*       hout = (l == 0) ? h1 : h0;
        k_knn2<<<BB, 512, knn_smem>>>(hin, kn);
        k_pre <<<NODES/256, 256>>>(hin, W_e0 + (size_t)l*2*HH*HH, b_e0 + l*HH, A, U);
        k_edge<<<NODES/16, 256, edge_smem>>>(A, U, kn, W_e1 + (size_t)l*HH*HH, b_e1 + l*HH, hout);
    }

    k_out<<<BB, 64>>>(h0, W_o0, b_o0, W_o1, b_o1, W_o2, b_o2, out);
}

// round 7
// speedup vs baseline: 1.4751x; 1.2121x over previous
#include <cuda_runtime.h>
#include <math.h>

#define BB   128
#define NN   512
#define FIN  5
#define HH   64
#define KNN  16
#define COUT 10
#define NODES (BB*NN)
#define HTS  520   // hT row stride in floats

typedef unsigned long long ull;

// ---------------- scratch (device globals) ----------------
__device__ float g_h0[NODES*HH];
__device__ float g_h1[NODES*HH];
__device__ float g_A [NODES*HH];
__device__ float g_U [NODES*HH];
__device__ int   g_knn[NODES*KNN];

// fast branchless ELU: __expf err ~2^-21 rel, fine vs 1e-3 tolerance
__device__ __forceinline__ float elu1(float x) {
    float e = __expf(x) - 1.f;
    return x > 0.f ? x : e;
}

// ---- packed f32x2 helpers (Blackwell FFMA2 via PTX) ----
__device__ __forceinline__ ull pack2(float x, float y) {
    ull r; asm("mov.b64 %0, {%1,%2};" : "=l"(r) : "f"(x), "f"(y)); return r;
}
__device__ __forceinline__ float2 unpack2(ull v) {
    float2 f; asm("mov.b64 {%0,%1}, %2;" : "=f"(f.x), "=f"(f.y) : "l"(v)); return f;
}
__device__ __forceinline__ ull ffma2(ull a, ull b, ull c) {
    ull d; asm("fma.rn.f32x2 %0, %1, %2, %3;" : "=l"(d) : "l"(a), "l"(b), "l"(c)); return d;
}

__device__ __forceinline__ unsigned fflip(float f) {
    unsigned u = __float_as_uint(f);
    return ((int)u < 0) ? ~u : (u | 0x80000000u);
}

// Batcher odd-even mergesort, n=16, in-register, fully unrolled
__device__ __forceinline__ void sort16(ull key[16]) {
#pragma unroll
    for (int p = 1; p < 16; p <<= 1) {
#pragma unroll
        for (int k = p; k >= 1; k >>= 1) {
#pragma unroll
            for (int j = k % p; j + k < 16; j += 2*k) {
#pragma unroll
                for (int ii = 0; ii < k; ii++) {
                    int a = ii + j, c = ii + j + k;
                    if (c < 16 && (a / (2*p) == c / (2*p))) {
                        ull lo = key[a] < key[c] ? key[a] : key[c];
                        ull hi = key[a] < key[c] ? key[c] : key[a];
                        key[a] = lo; key[c] = hi;
                    }
                }
            }
        }
    }
}

// ---------------- input layer 0 (IN=5) ----------------
__global__ __launch_bounds__(256) void k_lin5(const float* __restrict__ in,
                                              const float* __restrict__ W,
                                              const float* __restrict__ b,
                                              float* __restrict__ out)
{
    __shared__ float sW[FIN*HH];
    __shared__ float sb[HH];
    int tid = threadIdx.x;
    for (int i = tid; i < FIN*HH; i += 256) sW[i] = W[i];
    if (tid < HH) sb[tid] = b[tid];
    __syncthreads();

    int node = blockIdx.x * 256 + tid;
    float v[FIN];
#pragma unroll
    for (int d = 0; d < FIN; d++) v[d] = in[node*FIN + d];

    for (int o = 0; o < HH; o++) {
        float a = sb[o];
#pragma unroll
        for (int d = 0; d < FIN; d++) a += v[d] * sW[d*HH + o];
        out[node*HH + o] = elu1(a);
    }
}

// ---------------- 64x64 GEMV + ELU, float4 input, f32x2 packed FMA ----------------
__global__ __launch_bounds__(256) void k_lin64(const float* __restrict__ in,
                                               const float* __restrict__ W,
                                               const float* __restrict__ b,
                                               float* __restrict__ out)
{
    __shared__ __align__(16) float sW[HH*HH];
    __shared__ float sb[HH];
    int tid = threadIdx.x;
    for (int i = tid; i < HH*HH; i += 256) sW[i] = W[i];
    if (tid < HH) sb[tid] = b[tid];
    __syncthreads();

    int node = blockIdx.x * 256 + tid;
    float v[HH];
    {
        const float4* p = (const float4*)(in + (size_t)node * HH);
#pragma unroll
        for (int q = 0; q < 16; q++) {
            float4 t = p[q];
            v[4*q] = t.x; v[4*q+1] = t.y; v[4*q+2] = t.z; v[4*q+3] = t.w;
        }
    }

#pragma unroll 2
    for (int op = 0; op < 32; op++) {
        ull acc = 0ull;
#pragma unroll
        for (int d = 0; d < HH; d++) {
            ull hp = pack2(v[d], v[d]);
            ull wv = ((const ull*)(sW + d*HH))[op];
            acc = ffma2(hp, wv, acc);
        }
        float2 p = unpack2(acc);
        float2 o2 = make_float2(elu1(p.x + sb[2*op]), elu1(p.y + sb[2*op+1]));
        *(float2*)&out[node*HH + 2*op] = o2;
    }
}

// ---------------- fused kNN + EdgeConv-layer0 pre-GEMMs ----------------
// One block per batch (512 thr). Phase 1: distances + exact top-16 (4 rows/warp,
// local-mem sorted lists, 4-way interleaved REDUX extraction).
// Phase 2: A/U pre-GEMMs reading features from hT in smem (conflict-free LDS).
// smem: hT[64][HTS] 133KB + sq 2KB + sWb 16KB + sWd 16KB + sbp 256B = ~168KB
__global__ __launch_bounds__(512) void k_knn3(const float* __restrict__ h,
                                              const float* __restrict__ W0,
                                              const float* __restrict__ b0,
                                              int* __restrict__ kn,
                                              float* __restrict__ A,
                                              float* __restrict__ U)
{
    extern __shared__ __align__(16) char smraw[];
    float* hT  = (float*)smraw;                // [64][HTS]
    float* sq  = hT + HH*HTS;                  // [512]
    float* sWb = sq + NN;                      // [4096]
    float* sWd = sWb + HH*HH;                  // [4096]
    float* sbp = sWd + HH*HH;                  // [64]

    int b = blockIdx.x, tid = threadIdx.x;
    int w = tid >> 5, lane = tid & 31;
    const float* hb = h + (size_t)b * NN * HH;

    // stage EdgeConv layer-0 weights (for phase 2)
    for (int i = tid; i < HH*HH; i += 512) {
        float wa = W0[i];
        float wb = W0[HH*HH + i];
        sWb[i] = wb;
        sWd[i] = wa - wb;
    }
    if (tid < HH) sbp[tid] = b0[tid];

    // load + transpose features, fold in squared norms
    {
        const float4* src = (const float4*)(hb + (size_t)tid * HH);
        float s = 0.f;
#pragma unroll
        for (int q = 0; q < 16; q++) {
            float4 v = src[q];
            int d = q * 4;
            hT[(d+0)*HTS + tid] = v.x;
            hT[(d+1)*HTS + tid] = v.y;
            hT[(d+2)*HTS + tid] = v.z;
            hT[(d+3)*HTS + tid] = v.w;
            s += v.x*v.x + v.y*v.y + v.z*v.z + v.w*v.w;
        }
        sq[tid] = s;
    }
    __syncthreads();

    // ---------- phase 1: kNN, 8 passes x 4 rows/warp ----------
    ull loc[64];   // 4 sorted 16-lists (local memory: dynamically indexed pops)

#pragma unroll 1
    for (int pp = 0; pp < 8; pp++) {
        int i0 = pp*64 + w*4;

        ull acc[4][8];
#pragma unroll
        for (int r = 0; r < 4; r++)
#pragma unroll
            for (int t = 0; t < 8; t++) acc[r][t] = 0ull;

#pragma unroll 4
        for (int d = 0; d < HH; d++) {
            const float* rowp = hT + d*HTS;
            float4 xv = *(const float4*)(rowp + i0);
            ull xp0 = pack2(xv.x, xv.x), xp1 = pack2(xv.y, xv.y);
            ull xp2 = pack2(xv.z, xv.z), xp3 = pack2(xv.w, xv.w);
            const ull* bp = (const ull*)rowp;
#pragma unroll
            for (int t = 0; t < 8; t++) {
                ull bv = bp[lane + 32*t];
                acc[0][t] = ffma2(xp0, bv, acc[0][t]);
                acc[1][t] = ffma2(xp1, bv, acc[1][t]);
                acc[2][t] = ffma2(xp2, bv, acc[2][t]);
                acc[3][t] = ffma2(xp3, bv, acc[3][t]);
            }
        }

        // per row: build keys, sort, store sorted list to local
#pragma unroll 1
        for (int r = 0; r < 4; r++) {
            int i = i0 + r;
            float sqi = sq[i];
            ull key[16];
#pragma unroll
            for (int t = 0; t < 8; t++) {
                int p = lane + 32*t;
                float2 dp = unpack2(acc[r][t]);
                float2 sp = ((const float2*)sq)[p];
                float d0 = fmaf(-2.f, dp.x, sqi + sp.x);
                float d1 = fmaf(-2.f, dp.y, sqi + sp.y);
                int c0 = 2*p, c1 = 2*p + 1;
                key[2*t]   = (c0 == i) ? ~0ull : (((ull)fflip(d0) << 32) | (unsigned)c0);
                key[2*t+1] = (c1 == i) ? ~0ull : (((ull)fflip(d1) << 32) | (unsigned)c1);
            }
            sort16(key);
#pragma unroll
            for (int s = 0; s < 16; s++) loc[r*16 + s] = key[s];
        }

        // interleaved extraction: 4 rows advance together (4x ILP on REDUX chain)
        ull head[4]; int ptr[4]; unsigned res[4];
#pragma unroll
        for (int r = 0; r < 4; r++) { head[r] = loc[r*16]; ptr[r] = 0; res[r] = 0; }

#pragma unroll 1
        for (int rd = 0; rd < KNN; rd++) {
#pragma unroll
            for (int r = 0; r < 4; r++) {
                unsigned hi  = (unsigned)(head[r] >> 32);
                unsigned mhi = __reduce_min_sync(0xffffffffu, hi);
                unsigned lo  = (hi == mhi) ? (unsigned)head[r] : 0xffffffffu;
                unsigned mlo = __reduce_min_sync(0xffffffffu, lo);
                if (lane == rd) res[r] = mlo;
                bool win = (hi == mhi) & ((unsigned)head[r] == mlo);
                if (win) {
                    ptr[r]++;
                    head[r] = (ptr[r] < 16) ? loc[r*16 + ptr[r]] : ~0ull;
                }
            }
        }
#pragma unroll
        for (int r = 0; r < 4; r++)
            if (lane < KNN) kn[((size_t)b*NN + i0 + r)*KNN + lane] = (int)res[r];
    }

    // ---------- phase 2: A/U pre-GEMMs, features from hT (conflict-free LDS) ----------
    {
        int node = b*NN + tid;
        float hv[HH];
#pragma unroll
        for (int d = 0; d < HH; d++) hv[d] = hT[d*HTS + tid];

#pragma unroll 2
        for (int op = 0; op < 32; op++) {
            ull au = 0ull, ad = 0ull;
#pragma unroll
            for (int d = 0; d < HH; d++) {
                ull hp = pack2(hv[d], hv[d]);
                au = ffma2(hp, ((const ull*)(sWb + d*HH))[op], au);
                ad = ffma2(hp, ((const ull*)(sWd + d*HH))[op], ad);
            }
            float2 pu = unpack2(au);
            *(float2*)&U[(size_t)node*HH + 2*op] = pu;
            float2 pa = unpack2(ad);
            pa.x += sbp[2*op]; pa.y += sbp[2*op+1];
            *(float2*)&A[(size_t)node*HH + 2*op] = pa;
        }
    }
}

// ---------------- EdgeConv per-edge: 2 nodes/warp, 16 nodes/block, f32x2 FMA ----------------
__global__ __launch_bounds__(256) void k_edge(const float* __restrict__ A,
                                              const float* __restrict__ U,
                                              const int* __restrict__ kn,
                                              const float* __restrict__ W1,
                                              const float* __restrict__ b1,
                                              float* __restrict__ hout)
{
    extern __shared__ __align__(16) char esm[];
    float* sW  = (float*)esm;                      // [64*64]
    float* sb  = sW + HH*HH;                       // [64]
    float* e0s = sb + HH;                          // [16 nodes][64][20]

    int tid = threadIdx.x;
    for (int i = tid; i < HH*HH; i += 256) sW[i] = W1[i];
    if (tid < HH) sb[tid] = b1[tid];
    __syncthreads();

    int w = tid >> 5, l = tid & 31;
    int n0 = blockIdx.x * 16 + w*2;
    int n1 = n0 + 1;
    int base = n0 & ~(NN - 1);
    float a00 = A[n0*HH + l],  a01 = A[n0*HH + l + 32];
    float a10 = A[n1*HH + l],  a11 = A[n1*HH + l + 32];
    const int* kp0 = kn + n0*KNN;
    const int* kp1 = kn + n1*KNN;
    float* e0 = e0s + (size_t)(w*2)   * (HH*20);
    float* e1 = e0s + (size_t)(w*2+1) * (HH*20);

#pragma unroll
    for (int k = 0; k < KNN; k++) {
        const float* up0 = U + (size_t)(base + kp0[k]) * HH;
        e0[l*20 + k]      = elu1(a00 + up0[l]);
        e0[(l+32)*20 + k] = elu1(a01 + up0[l + 32]);
        const float* up1 = U + (size_t)(base + kp1[k]) * HH;
        e1[l*20 + k]      = elu1(a10 + up1[l]);
        e1[(l+32)*20 + k] = elu1(a11 + up1[l + 32]);
    }
    __syncwarp();

    ull v0a[8], v0b[8], v1a[8], v1b[8];
#pragma unroll
    for (int m = 0; m < 8; m++) { v0a[m]=0ull; v0b[m]=0ull; v1a[m]=0ull; v1b[m]=0ull; }

#pragma unroll 4
    for (int d = 0; d < HH; d++) {
        float w0 = sW[d*HH + l];
        float w1 = sW[d*HH + l + 32];
        ull w00 = pack2(w0, w0), w11 = pack2(w1, w1);
        const longlong2* ep0 = (const longlong2*)&e0[d*20];
        const longlong2* ep1 = (const longlong2*)&e1[d*20];
#pragma unroll
        for (int m = 0; m < 4; m++) {
            longlong2 q0 = ep0[m];
            v0a[2*m]   = ffma2((ull)q0.x, w00, v0a[2*m]);
            v0a[2*m+1] = ffma2((ull)q0.y, w00, v0a[2*m+1]);
            v0b[2*m]   = ffma2((ull)q0.x, w11, v0b[2*m]);
            v0b[2*m+1] = ffma2((ull)q0.y, w11, v0b[2*m+1]);
            longlong2 q1 = ep1[m];
            v1a[2*m]   = ffma2((ull)q1.x, w00, v1a[2*m]);
            v1a[2*m+1] = ffma2((ull)q1.y, w00, v1a[2*m+1]);
            v1b[2*m]   = ffma2((ull)q1.x, w11, v1b[2*m]);
            v1b[2*m+1] = ffma2((ull)q1.y, w11, v1b[2*m+1]);
        }
    }

    float bb0 = sb[l], bb1 = sb[l + 32];
    float o0a = 0.f, o0b = 0.f, o1a = 0.f, o1b = 0.f;
#pragma unroll
    for (int m = 0; m < 8; m++) {
        float2 p;
        p = unpack2(v0a[m]); o0a += elu1(p.x + bb0) + elu1(p.y + bb0);
        p = unpack2(v0b[m]); o0b += elu1(p.x + bb1) + elu1(p.y + bb1);
        p = unpack2(v1a[m]); o1a += elu1(p.x + bb0) + elu1(p.y + bb0);
        p = unpack2(v1b[m]); o1b += elu1(p.x + bb1) + elu1(p.y + bb1);
    }
    hout[n0*HH + l]      = o0a;
    hout[n0*HH + l + 32] = o0b;
    hout[n1*HH + l]      = o1a;
    hout[n1*HH + l + 32] = o1b;
}

// ---------------- global max-pool + output MLP + log_softmax ----------------
__global__ __launch_bounds__(64) void k_out(const float* __restrict__ h,
                                            const float* __restrict__ Wo0, const float* __restrict__ bo0,
                                            const float* __restrict__ Wo1, const float* __restrict__ bo1,
                                            const float* __restrict__ Wo2, const float* __restrict__ bo2,
                                            float* __restrict__ out)
{
    int b = blockIdx.x, o = threadIdx.x;
    __shared__ float s0[HH], s1[HH], slog[COUT + 1];
    const float* hb = h + (size_t)b * NN * HH;

    float m = -3.0e38f;
    for (int n = 0; n < NN; n++) m = fmaxf(m, hb[n*HH + o]);
    s0[o] = m;
    __syncthreads();

    float a = bo0[o];
    for (int d = 0; d < HH; d++) a += s0[d] * Wo0[d*HH + o];
    s1[o] = elu1(a);
    __syncthreads();

    a = bo1[o];
    for (int d = 0; d < HH; d++) a += s1[d] * Wo1[d*HH + o];
    __syncthreads();
    s0[o] = elu1(a);
    __syncthreads();

    if (o < COUT) {
        float lg = bo2[o];
        for (int d = 0; d < HH; d++) lg += s0[d] * Wo2[d*COUT + o];
        slog[o] = lg;
    }
    __syncthreads();
    if (o == 0) {
        float mx = -3.0e38f;
        for (int c = 0; c < COUT; c++) mx = fmaxf(mx, slog[c]);
        float s = 0.f;
        for (int c = 0; c < COUT; c++) s += expf(slog[c] - mx);
        slog[COUT] = mx + logf(s);
    }
    __syncthreads();
    if (o < COUT) out[b*COUT + o] = slog[o] - slog[COUT];
}

// ---------------- host launcher ----------------
extern "C" void kernel_launch(void* const* d_in, const int* in_sizes, int n_in,
                              void* d_out, int out_size)
{
    const float* x     = (const float*)d_in[0];
    const float* W_in0 = (const float*)d_in[1];
    const float* b_in0 = (const float*)d_in[2];
    const float* W_in1 = (const float*)d_in[3];
    const float* b_in1 = (const float*)d_in[4];
    const float* W_in2 = (const float*)d_in[5];
    const float* b_in2 = (const float*)d_in[6];
    const float* W_e0  = (const float*)d_in[7];
    const float* b_e0  = (const float*)d_in[8];
    const float* W_e1  = (const float*)d_in[9];
    const float* b_e1  = (const float*)d_in[10];
    const float* W_o0  = (const float*)d_in[11];
    const float* b_o0  = (const float*)d_in[12];
    const float* W_o1  = (const float*)d_in[13];
    const float* b_o1  = (const float*)d_in[14];
    const float* W_o2  = (const float*)d_in[15];
    const float* b_o2  = (const float*)d_in[16];
    float* out = (float*)d_out;

    float *h0, *h1, *A, *U;
    int* kn;
    cudaGetSymbolAddress((void**)&h0, g_h0);
    cudaGetSymbolAddress((void**)&h1, g_h1);
    cudaGetSymbolAddress((void**)&A,  g_A);
    cudaGetSymbolAddress((void**)&U,  g_U);
    cudaGetSymbolAddress((void**)&kn, g_knn);

    const int knn_smem  = (HH*HTS + NN + 2*HH*HH + HH) * sizeof(float);  // ~168KB
    const int edge_smem = (HH*HH + HH + 16*HH*20) * sizeof(float);       // ~98.6KB
    cudaFuncSetAttribute(k_knn3, cudaFuncAttributeMaxDynamicSharedMemorySize, knn_smem);
    cudaFuncSetAttribute(k_edge, cudaFuncAttributeMaxDynamicSharedMemorySize, edge_smem);

    // input MLP: x -> h1 -> A -> h0
    k_lin5 <<<NODES/256, 256>>>(x,  W_in0, b_in0, h1);
    k_lin64<<<NODES/256, 256>>>(h1, W_in1, b_in1, A);
    k_lin64<<<NODES/256, 256>>>(A,  W_in2, b_in2, h0);

    // 2 dynamic-kNN EdgeConv layers: h0 -> h1 -> h0
    for (int l = 0; l < 2; l++) {
        const float* hin  = (l == 0) ? h0 : h1;
        float*       hout = (l == 0) ? h1 : h0;
        k_knn3<<<BB, 512, knn_smem>>>(hin, W_e0 + (size_t)l*2*HH*HH, b_e0 + l*HH, kn, A, U);
        k_edge<<<NODES/16, 256, edge_smem>>>(A, U, kn, W_e1 + (size_t)l*HH*HH, b_e1 + l*HH, hout);
    }

    k_out<<<BB, 64>>>(h0, W_o0, b_o0, W_o1, b_o1, W_o2, b_o2, out);
}

// round 8
// speedup vs baseline: 1.6064x; 1.0890x over previous
#include <cuda_runtime.h>
#include <math.h>

#define BB   128
#define NN   512
#define FIN  5
#define HH   64
#define KNN  16
#define COUT 10
#define NODES (BB*NN)
#define HTS  520   // hT row stride in floats

typedef unsigned long long ull;

// ---------------- scratch (device globals) ----------------
__device__ float g_h0[NODES*HH];
__device__ float g_h1[NODES*HH];
__device__ float g_A [NODES*HH];
__device__ float g_U [NODES*HH];
__device__ int   g_knn[NODES*KNN];

// fast branchless ELU
__device__ __forceinline__ float elu1(float x) {
    float e = __expf(x) - 1.f;
    return x > 0.f ? x : e;
}

// ---- packed f32x2 helpers (Blackwell FFMA2 via PTX) ----
__device__ __forceinline__ ull pack2(float x, float y) {
    ull r; asm("mov.b64 %0, {%1,%2};" : "=l"(r) : "f"(x), "f"(y)); return r;
}
__device__ __forceinline__ float2 unpack2(ull v) {
    float2 f; asm("mov.b64 {%0,%1}, %2;" : "=f"(f.x), "=f"(f.y) : "l"(v)); return f;
}
__device__ __forceinline__ ull ffma2(ull a, ull b, ull c) {
    ull d; asm("fma.rn.f32x2 %0, %1, %2, %3;" : "=l"(d) : "l"(a), "l"(b), "l"(c)); return d;
}

__device__ __forceinline__ unsigned fflip(float f) {
    unsigned u = __float_as_uint(f);
    return ((int)u < 0) ? ~u : (u | 0x80000000u);
}

// Batcher odd-even mergesort, n=16, in-register, fully unrolled
__device__ __forceinline__ void sort16(ull key[16]) {
#pragma unroll
    for (int p = 1; p < 16; p <<= 1) {
#pragma unroll
        for (int k = p; k >= 1; k >>= 1) {
#pragma unroll
            for (int j = k % p; j + k < 16; j += 2*k) {
#pragma unroll
                for (int ii = 0; ii < k; ii++) {
                    int a = ii + j, c = ii + j + k;
                    if (c < 16 && (a / (2*p) == c / (2*p))) {
                        ull lo = key[a] < key[c] ? key[a] : key[c];
                        ull hi = key[a] < key[c] ? key[c] : key[a];
                        key[a] = lo; key[c] = hi;
                    }
                }
            }
        }
    }
}

// ---------------- input layer 0 (IN=5) ----------------
__global__ __launch_bounds__(256) void k_lin5(const float* __restrict__ in,
                                              const float* __restrict__ W,
                                              const float* __restrict__ b,
                                              float* __restrict__ out)
{
    __shared__ float sW[FIN*HH];
    __shared__ float sb[HH];
    int tid = threadIdx.x;
    for (int i = tid; i < FIN*HH; i += 256) sW[i] = W[i];
    if (tid < HH) sb[tid] = b[tid];
    __syncthreads();

    int node = blockIdx.x * 256 + tid;
    float v[FIN];
#pragma unroll
    for (int d = 0; d < FIN; d++) v[d] = in[node*FIN + d];

    for (int o = 0; o < HH; o++) {
        float a = sb[o];
#pragma unroll
        for (int d = 0; d < FIN; d++) a += v[d] * sW[d*HH + o];
        out[node*HH + o] = elu1(a);
    }
}

// ---------------- 64x64 GEMV + ELU ----------------
__global__ __launch_bounds__(256) void k_lin64(const float* __restrict__ in,
                                               const float* __restrict__ W,
                                               const float* __restrict__ b,
                                               float* __restrict__ out)
{
    __shared__ __align__(16) float sW[HH*HH];
    __shared__ float sb[HH];
    int tid = threadIdx.x;
    for (int i = tid; i < HH*HH; i += 256) sW[i] = W[i];
    if (tid < HH) sb[tid] = b[tid];
    __syncthreads();

    int node = blockIdx.x * 256 + tid;
    float v[HH];
    {
        const float4* p = (const float4*)(in + (size_t)node * HH);
#pragma unroll
        for (int q = 0; q < 16; q++) {
            float4 t = p[q];
            v[4*q] = t.x; v[4*q+1] = t.y; v[4*q+2] = t.z; v[4*q+3] = t.w;
        }
    }

#pragma unroll 2
    for (int op = 0; op < 32; op++) {
        ull acc = 0ull;
#pragma unroll
        for (int d = 0; d < HH; d++) {
            ull hp = pack2(v[d], v[d]);
            ull wv = ((const ull*)(sW + d*HH))[op];
            acc = ffma2(hp, wv, acc);
        }
        float2 p = unpack2(acc);
        float2 o2 = make_float2(elu1(p.x + sb[2*op]), elu1(p.y + sb[2*op+1]));
        *(float2*)&out[node*HH + 2*op] = o2;
    }
}

// ---------------- fused A/U pre-GEMMs + kNN, smem-union phased layout ----------------
// smem: hT[64][HTS] 130KB + sq 2KB + sbp 256B + union{ weights 32KB | sel 64KB } = ~196KB
// Phase A (weights live): A/U GEMV from hT. Phase B (sel live): distances + top-16.
__global__ __launch_bounds__(512) void k_knn3(const float* __restrict__ h,
                                              const float* __restrict__ W0,
                                              const float* __restrict__ b0,
                                              int* __restrict__ kn,
                                              float* __restrict__ A,
                                              float* __restrict__ U)
{
    extern __shared__ __align__(16) char smraw[];
    float* hT  = (float*)smraw;                // [64][HTS]
    float* sq  = hT + HH*HTS;                  // [512]
    float* sbp = sq + NN;                      // [64]
    float* uni = sbp + HH;                     // union region (16-B aligned)
    float* sWb = uni;                          // [4096] (phase A)
    float* sWd = uni + HH*HH;                  // [4096] (phase A)
    ull*   sel = (ull*)uni;                    // [16][16][32] (phase B)

    int b = blockIdx.x, tid = threadIdx.x;
    int w = tid >> 5, lane = tid & 31;
    const float* hb = h + (size_t)b * NN * HH;

    // stage EdgeConv layer-0 weights (phase A) + bias
    for (int i = tid; i < HH*HH; i += 512) {
        float wa = W0[i];
        float wb = W0[HH*HH + i];
        sWb[i] = wb;
        sWd[i] = wa - wb;
    }
    if (tid < HH) sbp[tid] = b0[tid];

    // load + transpose features, fold in squared norms
    {
        const float4* src = (const float4*)(hb + (size_t)tid * HH);
        float s = 0.f;
#pragma unroll
        for (int q = 0; q < 16; q++) {
            float4 v = src[q];
            int d = q * 4;
            hT[(d+0)*HTS + tid] = v.x;
            hT[(d+1)*HTS + tid] = v.y;
            hT[(d+2)*HTS + tid] = v.z;
            hT[(d+3)*HTS + tid] = v.w;
            s += v.x*v.x + v.y*v.y + v.z*v.z + v.w*v.w;
        }
        sq[tid] = s;
    }
    __syncthreads();

    // ---------- phase A: A/U pre-GEMMs (weights live in union) ----------
    {
        int node = b*NN + tid;
        float hv[HH];
#pragma unroll
        for (int d = 0; d < HH; d++) hv[d] = hT[d*HTS + tid];

#pragma unroll 2
        for (int op = 0; op < 32; op++) {
            ull au = 0ull, ad = 0ull;
#pragma unroll
            for (int d = 0; d < HH; d++) {
                ull hp = pack2(hv[d], hv[d]);
                au = ffma2(hp, ((const ull*)(sWb + d*HH))[op], au);
                ad = ffma2(hp, ((const ull*)(sWd + d*HH))[op], ad);
            }
            float2 pu = unpack2(au);
            *(float2*)&U[(size_t)node*HH + 2*op] = pu;
            float2 pa = unpack2(ad);
            pa.x += sbp[2*op]; pa.y += sbp[2*op+1];
            *(float2*)&A[(size_t)node*HH + 2*op] = pa;
        }
    }
    __syncthreads();   // all weight reads done; union becomes sel

    // ---------- phase B: kNN, 8 passes x 4 rows/warp ----------
    ull* wsel = sel + w * 16 * 32;

#pragma unroll 1
    for (int pp = 0; pp < 8; pp++) {
        int i0 = pp*64 + w*4;

        ull acc[4][8];
#pragma unroll
        for (int r = 0; r < 4; r++)
#pragma unroll
            for (int t = 0; t < 8; t++) acc[r][t] = 0ull;

#pragma unroll 4
        for (int d = 0; d < HH; d++) {
            const float* rowp = hT + d*HTS;
            float4 xv = *(const float4*)(rowp + i0);   // broadcast LDS.128
            ull xp0 = pack2(xv.x, xv.x), xp1 = pack2(xv.y, xv.y);
            ull xp2 = pack2(xv.z, xv.z), xp3 = pack2(xv.w, xv.w);
            const ull* bp = (const ull*)rowp;
#pragma unroll
            for (int t = 0; t < 8; t++) {
                ull bv = bp[lane + 32*t];
                acc[0][t] = ffma2(xp0, bv, acc[0][t]);
                acc[1][t] = ffma2(xp1, bv, acc[1][t]);
                acc[2][t] = ffma2(xp2, bv, acc[2][t]);
                acc[3][t] = ffma2(xp3, bv, acc[3][t]);
            }
        }

        // per row: keys -> sort16 -> spill sorted list to smem -> REDUX-min merge
#pragma unroll 1
        for (int r = 0; r < 4; r++) {
            int i = i0 + r;
            float sqi = sq[i];
            ull key[16];
#pragma unroll
            for (int t = 0; t < 8; t++) {
                int p = lane + 32*t;
                float2 dp = unpack2(acc[r][t]);
                float2 sp = ((const float2*)sq)[p];
                float d0 = fmaf(-2.f, dp.x, sqi + sp.x);
                float d1 = fmaf(-2.f, dp.y, sqi + sp.y);
                int c0 = 2*p, c1 = 2*p + 1;
                key[2*t]   = (c0 == i) ? ~0ull : (((ull)fflip(d0) << 32) | (unsigned)c0);
                key[2*t+1] = (c1 == i) ? ~0ull : (((ull)fflip(d1) << 32) | (unsigned)c1);
            }

            sort16(key);

#pragma unroll
            for (int s = 0; s < 16; s++) wsel[s*32 + lane] = key[s];
            __syncwarp();

            ull head = key[0];
            int ptr = 0; unsigned res = 0;
#pragma unroll
            for (int rd = 0; rd < KNN; rd++) {
                unsigned hi  = (unsigned)(head >> 32);
                unsigned mhi = __reduce_min_sync(0xffffffffu, hi);
                unsigned lo  = (hi == mhi) ? (unsigned)head : 0xffffffffu;
                unsigned mlo = __reduce_min_sync(0xffffffffu, lo);
                if (lane == rd) res = mlo;              // low 32 bits == column index
                bool win = (hi == mhi) & ((unsigned)head == mlo);  // unique -> one winner
                if (win) {
                    ptr++;
                    head = (ptr < 16) ? wsel[ptr*32 + lane] : ~0ull;
                }
            }
            if (lane < KNN) kn[((size_t)b*NN + i)*KNN + lane] = (int)res;
            __syncwarp();
        }
    }
}

// ---------------- EdgeConv per-edge: 2 nodes/warp, 16 nodes/block, f32x2 FMA ----------------
__global__ __launch_bounds__(256) void k_edge(const float* __restrict__ A,
                                              const float* __restrict__ U,
                                              const int* __restrict__ kn,
                                              const float* __restrict__ W1,
                                              const float* __restrict__ b1,
                                              float* __restrict__ hout)
{
    extern __shared__ __align__(16) char esm[];
    float* sW  = (float*)esm;                      // [64*64]
    float* sb  = sW + HH*HH;                       // [64]
    float* e0s = sb + HH;                          // [16 nodes][64][20]

    int tid = threadIdx.x;
    for (int i = tid; i < HH*HH; i += 256) sW[i] = W1[i];
    if (tid < HH) sb[tid] = b1[tid];
    __syncthreads();

    int w = tid >> 5, l = tid & 31;
    int n0 = blockIdx.x * 16 + w*2;
    int n1 = n0 + 1;
    int base = n0 & ~(NN - 1);
    float a00 = A[n0*HH + l],  a01 = A[n0*HH + l + 32];
    float a10 = A[n1*HH + l],  a11 = A[n1*HH + l + 32];
    const int* kp0 = kn + n0*KNN;
    const int* kp1 = kn + n1*KNN;
    float* e0 = e0s + (size_t)(w*2)   * (HH*20);
    float* e1 = e0s + (size_t)(w*2+1) * (HH*20);

#pragma unroll
    for (int k = 0; k < KNN; k++) {
        const float* up0 = U + (size_t)(base + kp0[k]) * HH;
        e0[l*20 + k]      = elu1(a00 + up0[l]);
        e0[(l+32)*20 + k] = elu1(a01 + up0[l + 32]);
        const float* up1 = U + (size_t)(base + kp1[k]) * HH;
        e1[l*20 + k]      = elu1(a10 + up1[l]);
        e1[(l+32)*20 + k] = elu1(a11 + up1[l + 32]);
    }
    __syncwarp();

    ull v0a[8], v0b[8], v1a[8], v1b[8];
#pragma unroll
    for (int m = 0; m < 8; m++) { v0a[m]=0ull; v0b[m]=0ull; v1a[m]=0ull; v1b[m]=0ull; }

#pragma unroll 4
    for (int d = 0; d < HH; d++) {
        float w0 = sW[d*HH + l];
        float w1 = sW[d*HH + l + 32];
        ull w00 = pack2(w0, w0), w11 = pack2(w1, w1);
        const longlong2* ep0 = (const longlong2*)&e0[d*20];
        const longlong2* ep1 = (const longlong2*)&e1[d*20];
#pragma unroll
        for (int m = 0; m < 4; m++) {
            longlong2 q0 = ep0[m];
            v0a[2*m]   = ffma2((ull)q0.x, w00, v0a[2*m]);
            v0a[2*m+1] = ffma2((ull)q0.y, w00, v0a[2*m+1]);
            v0b[2*m]   = ffma2((ull)q0.x, w11, v0b[2*m]);
            v0b[2*m+1] = ffma2((ull)q0.y, w11, v0b[2*m+1]);
            longlong2 q1 = ep1[m];
            v1a[2*m]   = ffma2((ull)q1.x, w00, v1a[2*m]);
            v1a[2*m+1] = ffma2((ull)q1.y, w00, v1a[2*m+1]);
            v1b[2*m]   = ffma2((ull)q1.x, w11, v1b[2*m]);
            v1b[2*m+1] = ffma2((ull)q1.y, w11, v1b[2*m+1]);
        }
    }

    float bb0 = sb[l], bb1 = sb[l + 32];
    float o0a = 0.f, o0b = 0.f, o1a = 0.f, o1b = 0.f;
#pragma unroll
    for (int m = 0; m < 8; m++) {
        float2 p;
        p = unpack2(v0a[m]); o0a += elu1(p.x + bb0) + elu1(p.y + bb0);
        p = unpack2(v0b[m]); o0b += elu1(p.x + bb1) + elu1(p.y + bb1);
        p = unpack2(v1a[m]); o1a += elu1(p.x + bb0) + elu1(p.y + bb0);
        p = unpack2(v1b[m]); o1b += elu1(p.x + bb1) + elu1(p.y + bb1);
    }
    hout[n0*HH + l]      = o0a;
    hout[n0*HH + l + 32] = o0b;
    hout[n1*HH + l]      = o1a;
    hout[n1*HH + l + 32] = o1b;
}

// ---------------- global max-pool + output MLP + log_softmax ----------------
__global__ __launch_bounds__(64) void k_out(const float* __restrict__ h,
                                            const float* __restrict__ Wo0, const float* __restrict__ bo0,
                                            const float* __restrict__ Wo1, const float* __restrict__ bo1,
                                            const float* __restrict__ Wo2, const float* __restrict__ bo2,
                                            float* __restrict__ out)
{
    int b = blockIdx.x, o = threadIdx.x;
    __shared__ float s0[HH], s1[HH], slog[COUT + 1];
    const float* hb = h + (size_t)b * NN * HH;

    float m = -3.0e38f;
    for (int n = 0; n < NN; n++) m = fmaxf(m, hb[n*HH + o]);
    s0[o] = m;
    __syncthreads();

    float a = bo0[o];
    for (int d = 0; d < HH; d++) a += s0[d] * Wo0[d*HH + o];
    s1[o] = elu1(a);
    __syncthreads();

    a = bo1[o];
    for (int d = 0; d < HH; d++) a += s1[d] * Wo1[d*HH + o];
    __syncthreads();
    s0[o] = elu1(a);
    __syncthreads();

    if (o < COUT) {
        float lg = bo2[o];
        for (int d = 0; d < HH; d++) lg += s0[d] * Wo2[d*COUT + o];
        slog[o] = lg;
    }
    __syncthreads();
    if (o == 0) {
        float mx = -3.0e38f;
        for (int c = 0; c < COUT; c++) mx = fmaxf(mx, slog[c]);
        float s = 0.f;
        for (int c = 0; c < COUT; c++) s += expf(slog[c] - mx);
        slog[COUT] = mx + logf(s);
    }
    __syncthreads();
    if (o < COUT) out[b*COUT + o] = slog[o] - slog[COUT];
}

// ---------------- host launcher ----------------
extern "C" void kernel_launch(void* const* d_in, const int* in_sizes, int n_in,
                              void* d_out, int out_size)
{
    const float* x     = (const float*)d_in[0];
    const float* W_in0 = (const float*)d_in[1];
    const float* b_in0 = (const float*)d_in[2];
    const float* W_in1 = (const float*)d_in[3];
    const float* b_in1 = (const float*)d_in[4];
    const float* W_in2 = (const float*)d_in[5];
    const float* b_in2 = (const float*)d_in[6];
    const float* W_e0  = (const float*)d_in[7];
    const float* b_e0  = (const float*)d_in[8];
    const float* W_e1  = (const float*)d_in[9];
    const float* b_e1  = (const float*)d_in[10];
    const float* W_o0  = (const float*)d_in[11];
    const float* b_o0  = (const float*)d_in[12];
    const float* W_o1  = (const float*)d_in[13];
    const float* b_o1  = (const float*)d_in[14];
    const float* W_o2  = (const float*)d_in[15];
    const float* b_o2  = (const float*)d_in[16];
    float* out = (float*)d_out;

    float *h0, *h1, *A, *U;
    int* kn;
    cudaGetSymbolAddress((void**)&h0, g_h0);
    cudaGetSymbolAddress((void**)&h1, g_h1);
    cudaGetSymbolAddress((void**)&A,  g_A);
    cudaGetSymbolAddress((void**)&U,  g_U);
    cudaGetSymbolAddress((void**)&kn, g_knn);

    // hT + sq + sbp + union(max(weights 32.25KB, sel 64KB))
    const int knn_smem  = (HH*HTS + NN + HH) * sizeof(float) + 16*16*32*sizeof(ull);
    const int edge_smem = (HH*HH + HH + 16*HH*20) * sizeof(float);
    cudaFuncSetAttribute(k_knn3, cudaFuncAttributeMaxDynamicSharedMemorySize, knn_smem);
    cudaFuncSetAttribute(k_edge, cudaFuncAttributeMaxDynamicSharedMemorySize, edge_smem);

    // input MLP: x -> h1 -> A -> h0
    k_lin5 <<<NODES/256, 256>>>(x,  W_in0, b_in0, h1);
    k_lin64<<<NODES/256, 256>>>(h1, W_in1, b_in1, A);
    k_lin64<<<NODES/256, 256>>>(A,  W_in2, b_in2, h0);

    // 2 dynamic-kNN EdgeConv layers: h0 -> h1 -> h0
    for (int l = 0; l < 2; l++) {
        const float* hin  = (l == 0) ? h0 : h1;
        float*       hout = (l == 0) ? h1 : h0;
        k_knn3<<<BB, 512, knn_smem>>>(hin, W_e0 + (size_t)l*2*HH*HH, b_e0 + l*HH, kn, A, U);
        k_edge<<<NODES/16, 256, edge_smem>>>(A, U, kn, W_e1 + (size_t)l*HH*HH, b_e1 + l*HH, hout);
    }

    k_out<<<BB, 64>>>(h0, W_o0, b_o0, W_o1, b_o1, W_o2, b_o2, out);
}